// round 14
// baseline (speedup 1.0000x reference)
#include <cuda_runtime.h>

#define Bsz 256
#define Tn  100
#define Fn  256
#define Hn  1024
#define On  8
#define NT  512   // scan threads per block

#define ALPHA 0.9048374180359595f   // exp(-0.001/0.01)
#define BETA  0.8187307530779818f   // exp(-0.001/0.005)

// Output layout: out [B,T+1,O], s1 [B,T,H], s2 [B,T,H], v1 [B,T,H], v2 [B,T,H]
#define S1_OFF  (Bsz*(Tn+1)*On)
#define S2_OFF  (S1_OFF + Bsz*Tn*Hn)
#define V1_OFF  (S2_OFF + Bsz*Tn*Hn)
#define V2_OFF  (V1_OFF + Bsz*Tn*Hn)

__device__ float g_H1[(size_t)Bsz * Tn * Hn];   // inputs @ W0

// ---------------------------------------------------------------------------
// fp32 SGEMM, occupancy-retiled: BM=64, BN=128, BK=8, double-buffered smem,
// 256 threads, 4x8 micro-tile (~64 regs -> 4 blocks/SM vs 2). Sequential-k
// FFMA chain per output element — association identical to reference.
// ---------------------------------------------------------------------------
__global__ __launch_bounds__(256) void sgemm_kernel(
    const float* __restrict__ A, const float* __restrict__ B,
    float* __restrict__ C, int M, int N, int K)
{
    __shared__ float As[2][8][64];
    __shared__ float Bs[2][8][128];

    int tid  = threadIdx.x;
    int brow = blockIdx.y * 64;
    int bcol = blockIdx.x * 128;

    int arow = tid >> 2;            // 0..63
    int acol = (tid & 3) << 1;      // 0,2,4,6
    int brw  = tid >> 5;            // 0..7
    int bcl  = (tid & 31) << 2;     // 0..124

    int ty = (tid >> 4) << 2;       // 0..60
    int tx = (tid & 15) << 3;       // 0..120

    float acc[4][8];
#pragma unroll
    for (int i = 0; i < 4; i++)
#pragma unroll
        for (int j = 0; j < 8; j++) acc[i][j] = 0.f;

    // Prologue: stage k0 = 0 into buffer 0.
    {
        float2 a2 = *(const float2*)(A + (size_t)(brow + arow) * K + acol);
        As[0][acol + 0][arow] = a2.x;
        As[0][acol + 1][arow] = a2.y;
        *(float4*)&Bs[0][brw][bcl] =
            *(const float4*)(B + (size_t)brw * N + bcol + bcl);
    }
    __syncthreads();

    int p = 0;
    for (int k0 = 0; k0 < K; k0 += 8) {
        bool more = (k0 + 8) < K;
        float2 na;
        float4 nb;
        if (more) {
            na = *(const float2*)(A + (size_t)(brow + arow) * K + (k0 + 8) + acol);
            nb = *(const float4*)(B + (size_t)(k0 + 8 + brw) * N + bcol + bcl);
        }

#pragma unroll
        for (int kk = 0; kk < 8; kk++) {
            float ar[4], br[8];
#pragma unroll
            for (int i = 0; i < 4; i++) ar[i] = As[p][kk][ty + i];
#pragma unroll
            for (int j = 0; j < 8; j++) br[j] = Bs[p][kk][tx + j];
#pragma unroll
            for (int i = 0; i < 4; i++)
#pragma unroll
                for (int j = 0; j < 8; j++)
                    acc[i][j] = __fmaf_rn(ar[i], br[j], acc[i][j]);
        }

        if (more) {
            int q = p ^ 1;
            As[q][acol + 0][arow] = na.x;
            As[q][acol + 1][arow] = na.y;
            *(float4*)&Bs[q][brw][bcl] = nb;
        }
        __syncthreads();
        p ^= 1;
    }

#pragma unroll
    for (int i = 0; i < 4; i++) {
        float4 c0 = make_float4(acc[i][0], acc[i][1], acc[i][2], acc[i][3]);
        float4 c1 = make_float4(acc[i][4], acc[i][5], acc[i][6], acc[i][7]);
        *(float4*)(C + (size_t)(brow + ty + i) * N + bcol + tx)     = c0;
        *(float4*)(C + (size_t)(brow + ty + i) * N + bcol + tx + 4) = c1;
    }
}

// ---------------------------------------------------------------------------
// Deterministic compact ascending-index list from per-thread float2 spikes.
// NT=512 threads, <=2 candidates each, 16-warp scan. Ends synced. (R9 exact.)
// ---------------------------------------------------------------------------
__device__ __forceinline__ int build_list2(float2 s, int* __restrict__ list,
                                           int* __restrict__ wscan)
{
    int tid  = threadIdx.x;
    int lane = tid & 31;
    int wid  = tid >> 5;

    int idx[2];
    int c = 0;
    int base = tid << 1;
    if (s.x != 0.f) idx[c++] = base;
    if (s.y != 0.f) idx[c++] = base + 1;

    int inc = c;
#pragma unroll
    for (int d = 1; d < 32; d <<= 1) {
        int n = __shfl_up_sync(0xffffffffu, inc, d);
        if (lane >= d) inc += n;
    }
    if (lane == 31) wscan[wid] = inc;
    __syncthreads();
    if (tid == 0) {
        int run = 0;
#pragma unroll
        for (int w = 0; w < 16; w++) { int v = wscan[w]; wscan[w] = run; run += v; }
        wscan[16] = run;
    }
    __syncthreads();
    int start = wscan[wid] + inc - c;
    if (c > 0) list[start] = idx[0];
    if (c > 1) list[start + 1] = idx[1];
    int total = wscan[16];
    __syncthreads();
    return total;
}

#define ACC2(a, r) { (a).x += (r).x; (a).y += (r).y; }
#define ROW2(M, k) (((const float2*)((M) + ((size_t)(k) << 10)))[tid])

// ---------------------------------------------------------------------------
// Triple gather, one phase: streams A=W1 and B=R0 share listL (count cL),
// stream C=R1 uses listM (count cM). Interleaved for max MLP (unroll 4+4+4).
// Per-stream adds in ascending list order -> bit-exact vs sequential. (R9.)
// ---------------------------------------------------------------------------
__device__ __forceinline__ void triple_gather2(
    const float* __restrict__ MA, const float* __restrict__ MB,
    const int* __restrict__ listL, int cL,
    const float* __restrict__ MC,
    const int* __restrict__ listM, int cM,
    float2& aA, float2& aB, float2& aC)
{
    int tid = threadIdx.x;
    aA = make_float2(0.f, 0.f);
    aB = make_float2(0.f, 0.f);
    aC = make_float2(0.f, 0.f);

    int cmin = min(cL, cM);
    int k = 0;
    for (; k + 4 <= cmin; k += 4) {
        int i0 = listL[k+0], i1 = listL[k+1], i2 = listL[k+2], i3 = listL[k+3];
        int j0 = listM[k+0], j1 = listM[k+1], j2 = listM[k+2], j3 = listM[k+3];
        float2 a0 = ROW2(MA, i0); float2 a1 = ROW2(MA, i1);
        float2 a2 = ROW2(MA, i2); float2 a3 = ROW2(MA, i3);
        float2 b0 = ROW2(MB, i0); float2 b1 = ROW2(MB, i1);
        float2 b2 = ROW2(MB, i2); float2 b3 = ROW2(MB, i3);
        float2 c0 = ROW2(MC, j0); float2 c1 = ROW2(MC, j1);
        float2 c2 = ROW2(MC, j2); float2 c3 = ROW2(MC, j3);
        ACC2(aA, a0); ACC2(aA, a1); ACC2(aA, a2); ACC2(aA, a3);
        ACC2(aB, b0); ACC2(aB, b1); ACC2(aB, b2); ACC2(aB, b3);
        ACC2(aC, c0); ACC2(aC, c1); ACC2(aC, c2); ACC2(aC, c3);
    }
    int kl = k;
    for (; kl + 4 <= cL; kl += 4) {
        int i0 = listL[kl+0], i1 = listL[kl+1], i2 = listL[kl+2], i3 = listL[kl+3];
        float2 a0 = ROW2(MA, i0); float2 a1 = ROW2(MA, i1);
        float2 a2 = ROW2(MA, i2); float2 a3 = ROW2(MA, i3);
        float2 b0 = ROW2(MB, i0); float2 b1 = ROW2(MB, i1);
        float2 b2 = ROW2(MB, i2); float2 b3 = ROW2(MB, i3);
        ACC2(aA, a0); ACC2(aA, a1); ACC2(aA, a2); ACC2(aA, a3);
        ACC2(aB, b0); ACC2(aB, b1); ACC2(aB, b2); ACC2(aB, b3);
    }
    for (; kl < cL; kl++) {
        int i = listL[kl];
        float2 a = ROW2(MA, i); float2 b = ROW2(MB, i);
        ACC2(aA, a); ACC2(aB, b);
    }
    int km = k;
    for (; km + 8 <= cM; km += 8) {
        float2 r0 = ROW2(MC, listM[km+0]); float2 r1 = ROW2(MC, listM[km+1]);
        float2 r2 = ROW2(MC, listM[km+2]); float2 r3 = ROW2(MC, listM[km+3]);
        float2 r4 = ROW2(MC, listM[km+4]); float2 r5 = ROW2(MC, listM[km+5]);
        float2 r6 = ROW2(MC, listM[km+6]); float2 r7 = ROW2(MC, listM[km+7]);
        ACC2(aC, r0); ACC2(aC, r1); ACC2(aC, r2); ACC2(aC, r3);
        ACC2(aC, r4); ACC2(aC, r5); ACC2(aC, r6); ACC2(aC, r7);
    }
    for (; km < cM; km++) { float2 r = ROW2(MC, listM[km]); ACC2(aC, r); }
}

// LIF update, FMA-contracted (bit-exact vs reference).
__device__ __forceinline__ void lif_update(float cur, float pot, float h, float rec,
                                           float& ncur, float& npot, float& spk)
{
    float x = __fadd_rn(pot, -1.0f);
    spk = (x > 0.f) ? 1.f : 0.f;
    float active = __fadd_rn(1.0f, -spk);
    ncur = __fadd_rn(__fmaf_rn(ALPHA, cur, h), rec);
    npot = __fmul_rn(__fmaf_rn(BETA, pot, ncur), active);
}

__device__ __forceinline__ void lif_update2(float2 cur, float2 pot, float2 h, float2 rec,
                                            float2& ncur, float2& npot, float2& spk)
{
    lif_update(cur.x, pot.x, h.x, rec.x, ncur.x, npot.x, spk.x);
    lif_update(cur.y, pot.y, h.y, rec.y, ncur.y, npot.y, spk.y);
}

// ---------------------------------------------------------------------------
// Persistent fused scan (R9 verbatim): one gather phase per step:
//   update1 -> build list1(spk1[t]) -> triple gather
//   (h2=W1@l1, rec1'=R0@l1, rec2=R1@l2(spk2[t-1])) -> update2 -> readout
//   -> build list2(spk2[t]).
// ---------------------------------------------------------------------------
__global__ __launch_bounds__(NT) void snn_scan_kernel(
    const float* __restrict__ R0, const float* __restrict__ W1,
    const float* __restrict__ R1, const float* __restrict__ Wout,
    float* __restrict__ out,
    float* __restrict__ s1g, float* __restrict__ s2g,
    float* __restrict__ v1g, float* __restrict__ v2g)
{
    __shared__ float sWout[Hn * On];   // 32 KB
    __shared__ int   list1[Hn];
    __shared__ int   list2[Hn];
    __shared__ int   wscan[17];
    __shared__ float wsum[16][On];

    int b    = blockIdx.x;
    int tid  = threadIdx.x;
    int lane = tid & 31;
    int wid  = tid >> 5;

#pragma unroll
    for (int i = 0; i < 4; i++)
        ((float4*)sWout)[tid + NT * i] = ((const float4*)Wout)[tid + NT * i];

    if (tid < On) out[(size_t)b * (Tn + 1) * On + tid] = 0.f;

    float2 z = make_float2(0.f, 0.f);
    float2 cur1 = z, pot1 = z, spk1 = z;
    float2 cur2 = z, pot2 = z, spk2 = z;
    float2 rec1 = z;              // R0@spk1[t-1], carried across steps
    int c2 = 0;                   // list2 count (spk2[t-1])
    float cur_ro = 0.f, pot_ro = 0.f;

    const float* h1base = g_H1 + (size_t)b * Tn * Hn;
    size_t rowbase = (size_t)b * Tn * Hn;

    __syncthreads();

    for (int t = 0; t < Tn; t++) {
        // ---- layer 1 update (rec1 precomputed last step) ----
        float2 h1 = ((const float2*)(h1base + (size_t)t * Hn))[tid];
        float2 ncur, npot;
        lif_update2(cur1, pot1, h1, rec1, ncur, npot, spk1);
        cur1 = ncur; pot1 = npot;
        ((float2*)(v1g + rowbase + (size_t)t * Hn))[tid] = pot1;
        ((float2*)(s1g + rowbase + (size_t)t * Hn))[tid] = spk1;

        // ---- build list1 from spk1[t] (internal syncs) ----
        int c1 = build_list2(spk1, list1, wscan);

        // ---- single triple-gather phase ----
        float2 h2, rec1n, rec2;
        triple_gather2(W1, R0, list1, c1, R1, list2, c2, h2, rec1n, rec2);
        rec1 = rec1n;

        // ---- layer 2 update ----
        lif_update2(cur2, pot2, h2, rec2, ncur, npot, spk2);
        cur2 = ncur; pot2 = npot;
        ((float2*)(v2g + rowbase + (size_t)t * Hn))[tid] = pot2;
        ((float2*)(s2g + rowbase + (size_t)t * Hn))[tid] = spk2;

        // ---- readout: h_ro = s2[t] @ Wout, leaky double integrator ----
        float pacc[On];
#pragma unroll
        for (int o = 0; o < On; o++) pacc[o] = 0.f;
        int base = tid << 1;
        if (spk2.x != 0.f) {
#pragma unroll
            for (int o = 0; o < On; o++) pacc[o] += sWout[(base + 0) * On + o];
        }
        if (spk2.y != 0.f) {
#pragma unroll
            for (int o = 0; o < On; o++) pacc[o] += sWout[(base + 1) * On + o];
        }
#pragma unroll
        for (int o = 0; o < On; o++) {
            float v = pacc[o];
#pragma unroll
            for (int off = 16; off; off >>= 1)
                v += __shfl_down_sync(0xffffffffu, v, off);
            if (lane == 0) wsum[wid][o] = v;
        }
        __syncthreads();
        if (tid < On) {
            float tot = 0.f;
#pragma unroll
            for (int w = 0; w < 16; w++) tot += wsum[w][tid];
            cur_ro = __fmaf_rn(ALPHA, cur_ro, tot);
            pot_ro = __fmaf_rn(BETA, pot_ro, cur_ro);
            out[(size_t)b * (Tn + 1) * On + (size_t)(t + 1) * On + tid] = pot_ro;
        }
        __syncthreads();

        // ---- build list2 from spk2[t] for next step's gather ----
        c2 = build_list2(spk2, list2, wscan);
    }
}

extern "C" void kernel_launch(void* const* d_in, const int* in_sizes, int n_in,
                              void* d_out, int out_size)
{
    const float* inputs = (const float*)d_in[0];
    const float* W0     = (const float*)d_in[1];
    const float* W1     = (const float*)d_in[2];
    const float* R0     = (const float*)d_in[3];
    const float* R1     = (const float*)d_in[4];
    const float* Wout   = (const float*)d_in[5];

    float* out = (float*)d_out;
    float* s1 = out + S1_OFF;
    float* s2 = out + S2_OFF;
    float* v1 = out + V1_OFF;
    float* v2 = out + V2_OFF;

    float* h1ptr = nullptr;
    cudaGetSymbolAddress((void**)&h1ptr, g_H1);

    // H1 = inputs @ W0 : [25600,256] @ [256,1024], BM=64 tiles for occupancy.
    {
        dim3 grid(Hn / 128, (Bsz * Tn) / 64);
        sgemm_kernel<<<grid, 256>>>(inputs, W0, h1ptr, Bsz * Tn, Hn, Fn);
    }

    // Fused persistent scan: one block per batch row.
    snn_scan_kernel<<<Bsz, NT>>>(R0, W1, R1, Wout, out, s1, s2, v1, v2);
}

// round 15
// speedup vs baseline: 1.0479x; 1.0479x over previous
#include <cuda_runtime.h>

#define Bsz 256
#define Tn  100
#define Fn  256
#define Hn  1024
#define On  8
#define NT  512   // scan threads per block

#define ALPHA 0.9048374180359595f   // exp(-0.001/0.01)
#define BETA  0.8187307530779818f   // exp(-0.001/0.005)

// Output layout: out [B,T+1,O], s1 [B,T,H], s2 [B,T,H], v1 [B,T,H], v2 [B,T,H]
#define S1_OFF  (Bsz*(Tn+1)*On)
#define S2_OFF  (S1_OFF + Bsz*Tn*Hn)
#define V1_OFF  (S2_OFF + Bsz*Tn*Hn)
#define V2_OFF  (V1_OFF + Bsz*Tn*Hn)

__device__ float g_H1[(size_t)Bsz * Tn * Hn];   // inputs @ W0

// ---------------------------------------------------------------------------
// fp32 SGEMM, 128x128 tile, BK=8, double-buffered smem (1 sync/iter), 8x8
// micro-tile. Sequential-k FFMA chain per output element — association
// identical to reference (bit-exact). Measured ~300us (R8/R9); both retile
// directions regressed (R14) — converged.
// ---------------------------------------------------------------------------
__global__ __launch_bounds__(256) void sgemm_kernel(
    const float* __restrict__ A, const float* __restrict__ B,
    float* __restrict__ C, int M, int N, int K)
{
    __shared__ float As[2][8][128];
    __shared__ float Bs[2][8][128];

    int tid  = threadIdx.x;
    int brow = blockIdx.y * 128;
    int bcol = blockIdx.x * 128;

    int arow = tid >> 1;
    int acol = (tid & 1) << 2;
    int brw  = tid >> 5;
    int bcl  = (tid & 31) << 2;
    int ty = (tid >> 4) << 3;
    int tx = (tid & 15) << 3;

    float acc[8][8];
#pragma unroll
    for (int i = 0; i < 8; i++)
#pragma unroll
        for (int j = 0; j < 8; j++) acc[i][j] = 0.f;

    {
        float4 a4 = *(const float4*)(A + (size_t)(brow + arow) * K + acol);
        As[0][acol + 0][arow] = a4.x;
        As[0][acol + 1][arow] = a4.y;
        As[0][acol + 2][arow] = a4.z;
        As[0][acol + 3][arow] = a4.w;
        *(float4*)&Bs[0][brw][bcl] =
            *(const float4*)(B + (size_t)brw * N + bcol + bcl);
    }
    __syncthreads();

    int p = 0;
    for (int k0 = 0; k0 < K; k0 += 8) {
        bool more = (k0 + 8) < K;
        float4 na, nb;
        if (more) {
            na = *(const float4*)(A + (size_t)(brow + arow) * K + (k0 + 8) + acol);
            nb = *(const float4*)(B + (size_t)(k0 + 8 + brw) * N + bcol + bcl);
        }

#pragma unroll
        for (int kk = 0; kk < 8; kk++) {
            float ar[8], br[8];
#pragma unroll
            for (int i = 0; i < 8; i++) ar[i] = As[p][kk][ty + i];
#pragma unroll
            for (int j = 0; j < 8; j++) br[j] = Bs[p][kk][tx + j];
#pragma unroll
            for (int i = 0; i < 8; i++)
#pragma unroll
                for (int j = 0; j < 8; j++)
                    acc[i][j] = __fmaf_rn(ar[i], br[j], acc[i][j]);
        }

        if (more) {
            int q = p ^ 1;
            As[q][acol + 0][arow] = na.x;
            As[q][acol + 1][arow] = na.y;
            As[q][acol + 2][arow] = na.z;
            As[q][acol + 3][arow] = na.w;
            *(float4*)&Bs[q][brw][bcl] = nb;
        }
        __syncthreads();
        p ^= 1;
    }

#pragma unroll
    for (int i = 0; i < 8; i++) {
        float4 c0 = make_float4(acc[i][0], acc[i][1], acc[i][2], acc[i][3]);
        float4 c1 = make_float4(acc[i][4], acc[i][5], acc[i][6], acc[i][7]);
        *(float4*)(C + (size_t)(brow + ty + i) * N + bcol + tx)     = c0;
        *(float4*)(C + (size_t)(brow + ty + i) * N + bcol + tx + 4) = c1;
    }
}

// ---------------------------------------------------------------------------
// Deterministic compact ascending-index list from per-thread float2 spikes.
// NT=512 threads, <=2 candidates each, 16-warp scan. Ends synced.
// ---------------------------------------------------------------------------
__device__ __forceinline__ int build_list2(float2 s, int* __restrict__ list,
                                           int* __restrict__ wscan)
{
    int tid  = threadIdx.x;
    int lane = tid & 31;
    int wid  = tid >> 5;

    int idx[2];
    int c = 0;
    int base = tid << 1;
    if (s.x != 0.f) idx[c++] = base;
    if (s.y != 0.f) idx[c++] = base + 1;

    int inc = c;
#pragma unroll
    for (int d = 1; d < 32; d <<= 1) {
        int n = __shfl_up_sync(0xffffffffu, inc, d);
        if (lane >= d) inc += n;
    }
    if (lane == 31) wscan[wid] = inc;
    __syncthreads();
    if (tid == 0) {
        int run = 0;
#pragma unroll
        for (int w = 0; w < 16; w++) { int v = wscan[w]; wscan[w] = run; run += v; }
        wscan[16] = run;
    }
    __syncthreads();
    int start = wscan[wid] + inc - c;
    if (c > 0) list[start] = idx[0];
    if (c > 1) list[start + 1] = idx[1];
    int total = wscan[16];
    __syncthreads();
    return total;
}

#define ACC2(a, r) { (a).x += (r).x; (a).y += (r).y; }
#define ROW2(M, k) (((const float2*)((M) + ((size_t)(k) << 10)))[tid])

// ---------------------------------------------------------------------------
// Triple gather, one phase: streams A=W1 and B=R0 share listL (count cL),
// stream C=R1 uses listM (count cM). Interleaved for max MLP (unroll 4+4+4).
// Per-stream adds in ascending list order -> bit-exact vs sequential.
// ---------------------------------------------------------------------------
__device__ __forceinline__ void triple_gather2(
    const float* __restrict__ MA, const float* __restrict__ MB,
    const int* __restrict__ listL, int cL,
    const float* __restrict__ MC,
    const int* __restrict__ listM, int cM,
    float2& aA, float2& aB, float2& aC)
{
    int tid = threadIdx.x;
    aA = make_float2(0.f, 0.f);
    aB = make_float2(0.f, 0.f);
    aC = make_float2(0.f, 0.f);

    int cmin = min(cL, cM);
    int k = 0;
    for (; k + 4 <= cmin; k += 4) {
        int i0 = listL[k+0], i1 = listL[k+1], i2 = listL[k+2], i3 = listL[k+3];
        int j0 = listM[k+0], j1 = listM[k+1], j2 = listM[k+2], j3 = listM[k+3];
        float2 a0 = ROW2(MA, i0); float2 a1 = ROW2(MA, i1);
        float2 a2 = ROW2(MA, i2); float2 a3 = ROW2(MA, i3);
        float2 b0 = ROW2(MB, i0); float2 b1 = ROW2(MB, i1);
        float2 b2 = ROW2(MB, i2); float2 b3 = ROW2(MB, i3);
        float2 c0 = ROW2(MC, j0); float2 c1 = ROW2(MC, j1);
        float2 c2 = ROW2(MC, j2); float2 c3 = ROW2(MC, j3);
        ACC2(aA, a0); ACC2(aA, a1); ACC2(aA, a2); ACC2(aA, a3);
        ACC2(aB, b0); ACC2(aB, b1); ACC2(aB, b2); ACC2(aB, b3);
        ACC2(aC, c0); ACC2(aC, c1); ACC2(aC, c2); ACC2(aC, c3);
    }
    int kl = k;
    for (; kl + 4 <= cL; kl += 4) {
        int i0 = listL[kl+0], i1 = listL[kl+1], i2 = listL[kl+2], i3 = listL[kl+3];
        float2 a0 = ROW2(MA, i0); float2 a1 = ROW2(MA, i1);
        float2 a2 = ROW2(MA, i2); float2 a3 = ROW2(MA, i3);
        float2 b0 = ROW2(MB, i0); float2 b1 = ROW2(MB, i1);
        float2 b2 = ROW2(MB, i2); float2 b3 = ROW2(MB, i3);
        ACC2(aA, a0); ACC2(aA, a1); ACC2(aA, a2); ACC2(aA, a3);
        ACC2(aB, b0); ACC2(aB, b1); ACC2(aB, b2); ACC2(aB, b3);
    }
    for (; kl < cL; kl++) {
        int i = listL[kl];
        float2 a = ROW2(MA, i); float2 b = ROW2(MB, i);
        ACC2(aA, a); ACC2(aB, b);
    }
    int km = k;
    for (; km + 8 <= cM; km += 8) {
        float2 r0 = ROW2(MC, listM[km+0]); float2 r1 = ROW2(MC, listM[km+1]);
        float2 r2 = ROW2(MC, listM[km+2]); float2 r3 = ROW2(MC, listM[km+3]);
        float2 r4 = ROW2(MC, listM[km+4]); float2 r5 = ROW2(MC, listM[km+5]);
        float2 r6 = ROW2(MC, listM[km+6]); float2 r7 = ROW2(MC, listM[km+7]);
        ACC2(aC, r0); ACC2(aC, r1); ACC2(aC, r2); ACC2(aC, r3);
        ACC2(aC, r4); ACC2(aC, r5); ACC2(aC, r6); ACC2(aC, r7);
    }
    for (; km < cM; km++) { float2 r = ROW2(MC, listM[km]); ACC2(aC, r); }
}

// LIF update, FMA-contracted (bit-exact vs reference).
__device__ __forceinline__ void lif_update(float cur, float pot, float h, float rec,
                                           float& ncur, float& npot, float& spk)
{
    float x = __fadd_rn(pot, -1.0f);
    spk = (x > 0.f) ? 1.f : 0.f;
    float active = __fadd_rn(1.0f, -spk);
    ncur = __fadd_rn(__fmaf_rn(ALPHA, cur, h), rec);
    npot = __fmul_rn(__fmaf_rn(BETA, pot, ncur), active);
}

__device__ __forceinline__ void lif_update2(float2 cur, float2 pot, float2 h, float2 rec,
                                            float2& ncur, float2& npot, float2& spk)
{
    lif_update(cur.x, pot.x, h.x, rec.x, ncur.x, npot.x, spk.x);
    lif_update(cur.y, pot.y, h.y, rec.y, ncur.y, npot.y, spk.y);
}

// ---------------------------------------------------------------------------
// Persistent fused scan (R9, converged): one gather phase per step:
//   update1 -> build list1(spk1[t]) -> triple gather
//   (h2=W1@l1, rec1'=R0@l1, rec2=R1@l2(spk2[t-1])) -> update2 -> readout
//   -> build list2(spk2[t]).
// ---------------------------------------------------------------------------
__global__ __launch_bounds__(NT) void snn_scan_kernel(
    const float* __restrict__ R0, const float* __restrict__ W1,
    const float* __restrict__ R1, const float* __restrict__ Wout,
    float* __restrict__ out,
    float* __restrict__ s1g, float* __restrict__ s2g,
    float* __restrict__ v1g, float* __restrict__ v2g)
{
    __shared__ float sWout[Hn * On];   // 32 KB
    __shared__ int   list1[Hn];
    __shared__ int   list2[Hn];
    __shared__ int   wscan[17];
    __shared__ float wsum[16][On];

    int b    = blockIdx.x;
    int tid  = threadIdx.x;
    int lane = tid & 31;
    int wid  = tid >> 5;

#pragma unroll
    for (int i = 0; i < 4; i++)
        ((float4*)sWout)[tid + NT * i] = ((const float4*)Wout)[tid + NT * i];

    if (tid < On) out[(size_t)b * (Tn + 1) * On + tid] = 0.f;

    float2 z = make_float2(0.f, 0.f);
    float2 cur1 = z, pot1 = z, spk1 = z;
    float2 cur2 = z, pot2 = z, spk2 = z;
    float2 rec1 = z;              // R0@spk1[t-1], carried across steps
    int c2 = 0;                   // list2 count (spk2[t-1])
    float cur_ro = 0.f, pot_ro = 0.f;

    const float* h1base = g_H1 + (size_t)b * Tn * Hn;
    size_t rowbase = (size_t)b * Tn * Hn;

    __syncthreads();

    for (int t = 0; t < Tn; t++) {
        // ---- layer 1 update (rec1 precomputed last step) ----
        float2 h1 = ((const float2*)(h1base + (size_t)t * Hn))[tid];
        float2 ncur, npot;
        lif_update2(cur1, pot1, h1, rec1, ncur, npot, spk1);
        cur1 = ncur; pot1 = npot;
        ((float2*)(v1g + rowbase + (size_t)t * Hn))[tid] = pot1;
        ((float2*)(s1g + rowbase + (size_t)t * Hn))[tid] = spk1;

        // ---- build list1 from spk1[t] (internal syncs) ----
        int c1 = build_list2(spk1, list1, wscan);

        // ---- single triple-gather phase ----
        float2 h2, rec1n, rec2;
        triple_gather2(W1, R0, list1, c1, R1, list2, c2, h2, rec1n, rec2);
        rec1 = rec1n;

        // ---- layer 2 update ----
        lif_update2(cur2, pot2, h2, rec2, ncur, npot, spk2);
        cur2 = ncur; pot2 = npot;
        ((float2*)(v2g + rowbase + (size_t)t * Hn))[tid] = pot2;
        ((float2*)(s2g + rowbase + (size_t)t * Hn))[tid] = spk2;

        // ---- readout: h_ro = s2[t] @ Wout, leaky double integrator ----
        float pacc[On];
#pragma unroll
        for (int o = 0; o < On; o++) pacc[o] = 0.f;
        int base = tid << 1;
        if (spk2.x != 0.f) {
#pragma unroll
            for (int o = 0; o < On; o++) pacc[o] += sWout[(base + 0) * On + o];
        }
        if (spk2.y != 0.f) {
#pragma unroll
            for (int o = 0; o < On; o++) pacc[o] += sWout[(base + 1) * On + o];
        }
#pragma unroll
        for (int o = 0; o < On; o++) {
            float v = pacc[o];
#pragma unroll
            for (int off = 16; off; off >>= 1)
                v += __shfl_down_sync(0xffffffffu, v, off);
            if (lane == 0) wsum[wid][o] = v;
        }
        __syncthreads();
        if (tid < On) {
            float tot = 0.f;
#pragma unroll
            for (int w = 0; w < 16; w++) tot += wsum[w][tid];
            cur_ro = __fmaf_rn(ALPHA, cur_ro, tot);
            pot_ro = __fmaf_rn(BETA, pot_ro, cur_ro);
            out[(size_t)b * (Tn + 1) * On + (size_t)(t + 1) * On + tid] = pot_ro;
        }
        __syncthreads();

        // ---- build list2 from spk2[t] for next step's gather ----
        c2 = build_list2(spk2, list2, wscan);
    }
}

extern "C" void kernel_launch(void* const* d_in, const int* in_sizes, int n_in,
                              void* d_out, int out_size)
{
    const float* inputs = (const float*)d_in[0];
    const float* W0     = (const float*)d_in[1];
    const float* W1     = (const float*)d_in[2];
    const float* R0     = (const float*)d_in[3];
    const float* R1     = (const float*)d_in[4];
    const float* Wout   = (const float*)d_in[5];

    float* out = (float*)d_out;
    float* s1 = out + S1_OFF;
    float* s2 = out + S2_OFF;
    float* v1 = out + V1_OFF;
    float* v2 = out + V2_OFF;

    float* h1ptr = nullptr;
    cudaGetSymbolAddress((void**)&h1ptr, g_H1);

    // H1 = inputs @ W0 : [25600,256] @ [256,1024]
    {
        dim3 grid(Hn / 128, (Bsz * Tn) / 128);
        sgemm_kernel<<<grid, 256>>>(inputs, W0, h1ptr, Bsz * Tn, Hn, Fn);
    }

    // Fused persistent scan: one block per batch row.
    snn_scan_kernel<<<Bsz, NT>>>(R0, W1, R1, Wout, out, s1, s2, v1, v2);
}